// round 9
// baseline (speedup 1.0000x reference)
#include <cuda_runtime.h>
#include <stdint.h>

#define HH 2048
#define WW 2048
#define NPIX (HH * WW)

#define TW 32                    // tile width
#define TH 16                    // tile height
#define SW (TW + 2)              // 34 (halo)
#define SH (TH + 2)              // 18 (halo)
#define NSLOT (SW * SH)          // 612

#define NBX 64                   // tiles per row (bits in a mask word)
#define NBY 128                  // tile rows
#define NB  (NBX * NBY)          // 8192

typedef unsigned long long ull;

__device__ float g_scratch[NPIX];
__device__ ull g_chmask[3][NBY];   // changed bits, 3-parity rotation
__device__ ull g_posmask[NBY];     // possible bits

// ---------------------------------------------------------------------------
// Threefry-2x32, 20 rounds — exact transcription of jax._src.prng
// ---------------------------------------------------------------------------
__host__ __device__ __forceinline__ uint32_t rotl32(uint32_t v, uint32_t r) {
#ifdef __CUDA_ARCH__
    return __funnelshift_l(v, v, r);
#else
    return (v << r) | (v >> (32u - r));
#endif
}

__host__ __device__ __forceinline__ void tf2x32(uint32_t k0, uint32_t k1,
                                                uint32_t x0, uint32_t x1,
                                                uint32_t& o0, uint32_t& o1) {
    uint32_t ks2 = k0 ^ k1 ^ 0x1BD11BDAu;
    x0 += k0; x1 += k1;
#define TF_R(r) { x0 += x1; x1 = rotl32(x1, r); x1 ^= x0; }
    TF_R(13u) TF_R(15u) TF_R(26u) TF_R(6u)
    x0 += k1;  x1 += ks2 + 1u;
    TF_R(17u) TF_R(29u) TF_R(16u) TF_R(24u)
    x0 += ks2; x1 += k0 + 2u;
    TF_R(13u) TF_R(15u) TF_R(26u) TF_R(6u)
    x0 += k0;  x1 += k1 + 3u;
    TF_R(17u) TF_R(29u) TF_R(16u) TF_R(24u)
    x0 += k1;  x1 += ks2 + 4u;
    TF_R(13u) TF_R(15u) TF_R(26u) TF_R(6u)
    x0 += ks2; x1 += k0 + 5u;
#undef TF_R
    o0 = x0; o1 = x1;
}

// Partitionable-mode random bits for flat index p: counter=(0,p); bits=o0^o1
__device__ __forceinline__ uint32_t pbits(uint32_t k0, uint32_t k1, uint32_t p) {
    uint32_t o0, o1;
    tf2x32(k0, k1, 0u, p, o0, o1);
    return o0 ^ o1;
}

__device__ __forceinline__ float bits_to_uniform(uint32_t bits) {
    return __fsub_rn(__uint_as_float((bits >> 9) | 0x3f800000u), 1.0f);
}

// ---------------------------------------------------------------------------
// x0 = seed * habitat * goodness  (+ reset masks)
// ---------------------------------------------------------------------------
__global__ void init_kernel(const float* __restrict__ seed,
                            const float* __restrict__ hab,
                            const float* __restrict__ good,
                            float* __restrict__ xout) {
    int idx = blockIdx.x * blockDim.x + threadIdx.x;
    if (idx < NPIX / 4) {
        const float4 s = ((const float4*)seed)[idx];
        const float4 h = ((const float4*)hab)[idx];
        const float4 g = ((const float4*)good)[idx];
        float4 o;
        o.x = __fmul_rn(__fmul_rn(s.x, h.x), g.x);
        o.y = __fmul_rn(__fmul_rn(s.y, h.y), g.y);
        o.z = __fmul_rn(__fmul_rn(s.z, h.z), g.z);
        o.w = __fmul_rn(__fmul_rn(s.w, h.w), g.w);
        ((float4*)xout)[idx] = o;
    }
    if (idx < NBY) {
        g_chmask[2][idx] = ~0ull;   // prev parity of iter 0 -> force all tiles
        g_chmask[0][idx] = 0ull;
        g_chmask[1][idx] = 0ull;
        g_posmask[idx]   = 0ull;
    }
}

// ---------------------------------------------------------------------------
// One spread step, one tile per block (8192 blocks).
//   y1 = x * (0.9999 + 1e-4*u1); y2 = maxpool3x3(y1); y3 = y2*(u2>0.5);
//   y4 = y3*goodness; x' = max(y4*((y4-x) > 0.05), x)
// Skip hierarchy (exact: good<1, noise factor <= 1):
//   tile masks -> pretest M-x>0.05 (no good load) -> exact pos -> gated RNG.
// ---------------------------------------------------------------------------
__global__ __launch_bounds__(256)
void step_kernel(const float* __restrict__ xin, float* __restrict__ xout,
                 const float* __restrict__ good,
                 uint32_t k1a, uint32_t k1b, uint32_t k2a, uint32_t k2b,
                 int prev, int cur, int nxt) {
    __shared__ float xs[SH][SW];     // raw x (tile + halo)
    __shared__ float ys[SH][SW];     // noised x (maxpool operand)
    __shared__ unsigned s_rowpos[TH];

    const int tid = threadIdx.x;
    const int tx = tid & 31;
    const int ty = tid >> 5;                     // 0..7

    // zero the next-parity mask row (not read or written this launch)
    if (blockIdx.x < NBY && tid == 0) g_chmask[nxt][blockIdx.x] = 0ull;

    const int by = blockIdx.x >> 6;
    const int bx = blockIdx.x & 63;

    // uniform mask loads (LDG broadcast)
    ull nbm = g_chmask[prev][by];
    const ull chm = nbm;
    if (by > 0)       nbm |= g_chmask[prev][by - 1];
    if (by < NBY - 1) nbm |= g_chmask[prev][by + 1];
    const ull posw = g_posmask[by];

    const ull colm = (bx == 0) ? 3ull : (7ull << (bx - 1));
    const bool need = ((nbm & colm) != 0ull) || (((posw >> bx) & 1ull) != 0ull);
    if (!need) return;                           // uniform across block

    const int selfchg = (int)((chm >> bx) & 1ull);
    const int c0 = bx * TW, r0 = by * TH;

    // ==== load tile: core via float4 (threads 0-127), halo ring (128-255) ====
    if (tid < 128) {
        int row = tid >> 3, q = tid & 7;
        const float4 v = *(const float4*)&xin[(r0 + row) * WW + c0 + q * 4];
        float* dst = &xs[row + 1][1 + q * 4];
        dst[0] = v.x; dst[1] = v.y; dst[2] = v.z; dst[3] = v.w;
    } else {
        int h = tid - 128;
        if (h < 100) {
            int j, i;
            if (h < 34)      { j = 0;             i = h; }
            else if (h < 68) { j = SH - 1;        i = h - 34; }
            else if (h < 84) { j = 1 + (h - 68);  i = 0; }
            else             { j = 1 + (h - 84);  i = SW - 1; }
            int r = r0 - 1 + j, c = c0 - 1 + i;
            bool ok = (r >= 0) && (r < HH) && (c >= 0) && (c < WW);
            xs[j][i] = ok ? xin[r * WW + c] : 0.0f;
        }
    }
    __syncthreads();

    // ==== pretest: M - x > 0.05 (no good load; pos => pre since good < 1) ====
    float xx[2], M[2];
    bool  pre[2];
    #pragma unroll
    for (int k = 0; k < 2; k++) {
        int jj = 1 + ty + k * 8, ii = 1 + tx;
        float m = xs[jj - 1][ii - 1];
        m = fmaxf(m, xs[jj - 1][ii    ]);
        m = fmaxf(m, xs[jj - 1][ii + 1]);
        m = fmaxf(m, xs[jj    ][ii - 1]);
        m = fmaxf(m, xs[jj    ][ii    ]);
        m = fmaxf(m, xs[jj    ][ii + 1]);
        m = fmaxf(m, xs[jj + 1][ii - 1]);
        m = fmaxf(m, xs[jj + 1][ii    ]);
        m = fmaxf(m, xs[jj + 1][ii + 1]);
        M[k]  = m;
        xx[k] = xs[jj][ii];
        pre[k] = __fsub_rn(m, xx[k]) > 0.05f;
    }
    int anyPre = __syncthreads_or((pre[0] || pre[1]) ? 1 : 0);

    float gd[2];
    bool  pos[2] = {false, false};
    int   any = 0;
    if (anyPre) {
        // ==== exact pos test (loads good; coalesced) ====
        #pragma unroll
        for (int k = 0; k < 2; k++) {
            int jj = 1 + ty + k * 8, ii = 1 + tx;
            int r = r0 + jj - 1, c = c0 + ii - 1;
            gd[k] = good[r * WW + c];
            pos[k] = pre[k] &&
                     (__fsub_rn(__fmul_rn(M[k], gd[k]), xx[k]) > 0.05f);
            unsigned rowmask = __ballot_sync(0xffffffffu, pos[k]);
            if (tx == 0) s_rowpos[ty + k * 8] = rowmask;
        }
        any = __syncthreads_or((pos[0] || pos[1]) ? 1 : 0);
    }

    if (!any) {
        // no update possible -> refresh out buffer only if stale
        if (selfchg) {
            #pragma unroll
            for (int k = 0; k < 2; k++) {
                int jj = 1 + ty + k * 8, ii = 1 + tx;
                int r = r0 + jj - 1, c = c0 + ii - 1;
                xout[r * WW + c] = xx[k];
            }
        }
        if (tid == 0 && ((posw >> bx) & 1ull))
            atomicAnd(&g_posmask[by], ~(1ull << bx));
        return;
    }

    // ==== fill noised tile, cipher gated on pos-mask dilated 1 px ====
    #pragma unroll
    for (int k = 0; k < 3; k++) {
        int s = tid + k * 256;
        bool sv = s < NSLOT;
        int ss = sv ? s : 0;
        int j = ss / SW, ii = ss % SW;
        float x = sv ? xs[j][ii] : 0.0f;
        unsigned rm = 0;
        #pragma unroll
        for (int dr = 0; dr < 3; dr++) {
            int cr = j - 2 + dr;
            if (cr >= 0 && cr < TH) rm |= s_rowpos[cr];
        }
        ull rm2 = ((ull)rm) << 2;
        bool needc = (((rm2 >> ii) & 7ull) != 0ull) && (x > 0.0f);
        float y1 = 0.0f;
        if (__ballot_sync(0xffffffffu, needc)) {
            int r = r0 - 1 + j, c = c0 - 1 + ii;
            uint32_t p = (uint32_t)(min(max(r, 0), HH - 1) * WW +
                                    min(max(c, 0), WW - 1));
            float u = bits_to_uniform(pbits(k1a, k1b, p));
            float f = __fadd_rn(0.9999f, __fmul_rn(1e-4f, u));
            y1 = __fmul_rn(x, f);
        }
        if (sv) ys[j][ii] = y1;
    }
    __syncthreads();

    // ==== maxpool + coin (cipher gated on pos) + write ====
    int chg = 0;
    #pragma unroll
    for (int k = 0; k < 2; k++) {
        int jj = 1 + ty + k * 8, ii = 1 + tx;
        float m = ys[jj - 1][ii - 1];
        m = fmaxf(m, ys[jj - 1][ii    ]);
        m = fmaxf(m, ys[jj - 1][ii + 1]);
        m = fmaxf(m, ys[jj    ][ii - 1]);
        m = fmaxf(m, ys[jj    ][ii    ]);
        m = fmaxf(m, ys[jj    ][ii + 1]);
        m = fmaxf(m, ys[jj + 1][ii - 1]);
        m = fmaxf(m, ys[jj + 1][ii    ]);
        m = fmaxf(m, ys[jj + 1][ii + 1]);

        int r = r0 + jj - 1, c = c0 + ii - 1;
        uint32_t p = (uint32_t)(r * WW + c);
        float y4 = 0.0f;
        if (__ballot_sync(0xffffffffu, pos[k])) {
            uint32_t bits = pbits(k2a, k2b, p);
            bool coin = ((bits >> 9) > 0x400000u);   // u > 0.5 strictly
            if (coin && m > 0.0f) y4 = __fmul_rn(m, gd[k]);
        }
        float d  = __fsub_rn(y4, xx[k]);
        float y5 = (d > 0.05f) ? y4 : 0.0f;
        float out = fmaxf(y5, xx[k]);
        xout[p] = out;
        chg |= (out != xx[k]) ? 1 : 0;
    }
    int anychg = __syncthreads_or(chg);
    if (tid == 0) {
        ull bit = 1ull << bx;
        if (anychg) atomicOr(&g_chmask[cur][by], bit);
        if (!((posw >> bx) & 1ull)) atomicOr(&g_posmask[by], bit);
    }
}

// ---------------------------------------------------------------------------
// Host: per-iteration key schedule (fold_in + partitionable split), ping-pong
// data buffers, 3-parity changed masks. 101 launches total.
// ---------------------------------------------------------------------------
extern "C" void kernel_launch(void* const* d_in, const int* in_sizes, int n_in,
                              void* d_out, int out_size) {
    const float* seed = (const float*)d_in[0];
    const float* hab  = (const float*)d_in[1];
    const float* good = (const float*)d_in[2];
    float* xout = (float*)d_out;

    float* scratch = nullptr;
    cudaGetSymbolAddress((void**)&scratch, g_scratch);

    init_kernel<<<(NPIX / 4 + 255) / 256, 256>>>(seed, hab, good, xout);

    for (int i = 0; i < 100; i++) {
        // fold_in(key(42)=(0,42), i) = cipher((0,42), (0,i))
        uint32_t f0, f1;
        tf2x32(0u, 42u, 0u, (uint32_t)i, f0, f1);
        // partitionable split: k1 = cipher(f,(0,0)), k2 = cipher(f,(0,1))
        uint32_t k1a, k1b, k2a, k2b;
        tf2x32(f0, f1, 0u, 0u, k1a, k1b);
        tf2x32(f0, f1, 0u, 1u, k2a, k2b);

        const int cur = i % 3, prev = (i + 2) % 3, nxt = (i + 1) % 3;
        const float* xin = (i & 1) ? scratch : xout;
        float*       xo  = (i & 1) ? xout    : scratch;

        step_kernel<<<NB, 256>>>(xin, xo, good, k1a, k1b, k2a, k2b,
                                 prev, cur, nxt);
    }
    // i = 99 (odd) wrote into xout -> final state lands in d_out
}

// round 10
// speedup vs baseline: 1.0691x; 1.0691x over previous
#include <cuda_runtime.h>
#include <stdint.h>

#define HH 2048
#define WW 2048
#define NPIX (HH * WW)

#define TW 32                    // tile width
#define TH 16                    // tile height
#define SW (TW + 2)              // 34 (halo)
#define SH (TH + 2)              // 18 (halo)
#define NSLOT (SW * SH)          // 612

#define NBX 64                   // tiles per row (bits in a mask word)
#define NBY 128                  // tile rows
#define NB  (NBX * NBY)          // 8192
#define TILES_PER_BLOCK 4
#define STEP_GRID (NB / TILES_PER_BLOCK)   // 2048

typedef unsigned long long ull;

__device__ float g_scratch[NPIX];
// edge-resolved changed masks, 3-parity rotation:
// [0]=any, [1]=top row, [2]=bottom row, [3]=left col, [4]=right col
__device__ ull g_ch[3][5][NBY];
__device__ ull g_posmask[NBY];     // possible bits

// ---------------------------------------------------------------------------
// Threefry-2x32, 20 rounds — exact transcription of jax._src.prng
// ---------------------------------------------------------------------------
__host__ __device__ __forceinline__ uint32_t rotl32(uint32_t v, uint32_t r) {
#ifdef __CUDA_ARCH__
    return __funnelshift_l(v, v, r);
#else
    return (v << r) | (v >> (32u - r));
#endif
}

__host__ __device__ __forceinline__ void tf2x32(uint32_t k0, uint32_t k1,
                                                uint32_t x0, uint32_t x1,
                                                uint32_t& o0, uint32_t& o1) {
    uint32_t ks2 = k0 ^ k1 ^ 0x1BD11BDAu;
    x0 += k0; x1 += k1;
#define TF_R(r) { x0 += x1; x1 = rotl32(x1, r); x1 ^= x0; }
    TF_R(13u) TF_R(15u) TF_R(26u) TF_R(6u)
    x0 += k1;  x1 += ks2 + 1u;
    TF_R(17u) TF_R(29u) TF_R(16u) TF_R(24u)
    x0 += ks2; x1 += k0 + 2u;
    TF_R(13u) TF_R(15u) TF_R(26u) TF_R(6u)
    x0 += k0;  x1 += k1 + 3u;
    TF_R(17u) TF_R(29u) TF_R(16u) TF_R(24u)
    x0 += k1;  x1 += ks2 + 4u;
    TF_R(13u) TF_R(15u) TF_R(26u) TF_R(6u)
    x0 += ks2; x1 += k0 + 5u;
#undef TF_R
    o0 = x0; o1 = x1;
}

// Partitionable-mode random bits for flat index p: counter=(0,p); bits=o0^o1
__device__ __forceinline__ uint32_t pbits(uint32_t k0, uint32_t k1, uint32_t p) {
    uint32_t o0, o1;
    tf2x32(k0, k1, 0u, p, o0, o1);
    return o0 ^ o1;
}

__device__ __forceinline__ float bits_to_uniform(uint32_t bits) {
    return __fsub_rn(__uint_as_float((bits >> 9) | 0x3f800000u), 1.0f);
}

// ---------------------------------------------------------------------------
// x0 = seed * habitat * goodness  (+ reset masks)
// ---------------------------------------------------------------------------
__global__ void init_kernel(const float* __restrict__ seed,
                            const float* __restrict__ hab,
                            const float* __restrict__ good,
                            float* __restrict__ xout) {
    int idx = blockIdx.x * blockDim.x + threadIdx.x;
    if (idx < NPIX / 4) {
        const float4 s = ((const float4*)seed)[idx];
        const float4 h = ((const float4*)hab)[idx];
        const float4 g = ((const float4*)good)[idx];
        float4 o;
        o.x = __fmul_rn(__fmul_rn(s.x, h.x), g.x);
        o.y = __fmul_rn(__fmul_rn(s.y, h.y), g.y);
        o.z = __fmul_rn(__fmul_rn(s.z, h.z), g.z);
        o.w = __fmul_rn(__fmul_rn(s.w, h.w), g.w);
        ((float4*)xout)[idx] = o;
    }
    if (idx < NBY) {
        #pragma unroll
        for (int e = 0; e < 5; e++) {
            g_ch[0][e][idx] = 0ull;
            g_ch[1][e][idx] = 0ull;
            g_ch[2][e][idx] = 0ull;
        }
        g_ch[2][0][idx] = ~0ull;   // prev parity of iter 0 -> force all tiles
        g_posmask[idx]  = 0ull;
    }
}

// ---------------------------------------------------------------------------
// One spread step, 4 adjacent tiles per block (2048 blocks).
//   y1 = x * (0.9999 + 1e-4*u1); y2 = maxpool3x3(y1); y3 = y2*(u2>0.5);
//   y4 = y3*goodness; x' = max(y4*((y4-x) > 0.05), x)
// Wake rule (exact): a tile needs compute iff it changed, has a possible
// cell, or a neighbor's *facing edge* changed (edge-resolved masks).
// Skip hierarchy: wake masks -> pretest M-x>0.05 (no good load, exact since
// good<1) -> exact pos -> RNG only on pos / dilated-pos cells.
// ---------------------------------------------------------------------------
__global__ __launch_bounds__(256)
void step_kernel(const float* __restrict__ xin, float* __restrict__ xout,
                 const float* __restrict__ good,
                 uint32_t k1a, uint32_t k1b, uint32_t k2a, uint32_t k2b,
                 int prev, int cur, int nxt) {
    __shared__ float xs[SH][SW];     // raw x (tile + halo)
    __shared__ float ys[SH][SW];     // noised x (maxpool operand)
    __shared__ unsigned s_rowpos[TH];
    __shared__ int s_flags;

    const int tid = threadIdx.x;
    const int tx = tid & 31;
    const int ty = tid >> 5;                     // 0..7

    // zero next-parity mask rows (not read or written this launch)
    if (blockIdx.x < NBY && tid < 5) g_ch[nxt][tid][blockIdx.x] = 0ull;

    const int tbase = blockIdx.x * TILES_PER_BLOCK;
    const int by  = tbase >> 6;
    const int bx0 = tbase & 63;

    // ==== edge-resolved wake computation (bit-parallel over the row) ====
    const ull chA = g_ch[prev][0][by];
    const ull chL = g_ch[prev][3][by];
    const ull chR = g_ch[prev][4][by];
    ull needw = chA | (chR << 1) | (chL >> 1);
    if (by > 0) {
        ull b = g_ch[prev][2][by - 1];           // above tile's bottom row
        ull l = g_ch[prev][3][by - 1], r = g_ch[prev][4][by - 1];
        needw |= b | ((b & r) << 1) | ((b & l) >> 1);
    }
    if (by < NBY - 1) {
        ull t = g_ch[prev][1][by + 1];           // below tile's top row
        ull l = g_ch[prev][3][by + 1], r = g_ch[prev][4][by + 1];
        needw |= t | ((t & r) << 1) | ((t & l) >> 1);
    }
    const ull posw = g_posmask[by];
    needw |= posw;

    #pragma unroll
    for (int kt = 0; kt < TILES_PER_BLOCK; kt++) {
        const int bx = bx0 + kt;
        if (!((needw >> bx) & 1ull)) continue;   // uniform across block

        const int selfchg = (int)((chA >> bx) & 1ull);
        const int c0 = bx * TW, r0 = by * TH;

        __syncthreads();                         // smem reuse barrier
        if (tid == 0) s_flags = 0;

        // ==== load tile: core via float4 (0-127), halo ring (128-255) ====
        if (tid < 128) {
            int row = tid >> 3, q = tid & 7;
            const float4 v = *(const float4*)&xin[(r0 + row) * WW + c0 + q * 4];
            float* dst = &xs[row + 1][1 + q * 4];
            dst[0] = v.x; dst[1] = v.y; dst[2] = v.z; dst[3] = v.w;
        } else {
            int h = tid - 128;
            if (h < 100) {
                int j, i;
                if (h < 34)      { j = 0;             i = h; }
                else if (h < 68) { j = SH - 1;        i = h - 34; }
                else if (h < 84) { j = 1 + (h - 68);  i = 0; }
                else             { j = 1 + (h - 84);  i = SW - 1; }
                int r = r0 - 1 + j, c = c0 - 1 + i;
                bool ok = (r >= 0) && (r < HH) && (c >= 0) && (c < WW);
                xs[j][i] = ok ? xin[r * WW + c] : 0.0f;
            }
        }
        __syncthreads();

        // ==== pretest: M - x > 0.05 (no good load; pos => pre) ====
        float xx[2], M[2];
        bool  pre[2];
        #pragma unroll
        for (int k = 0; k < 2; k++) {
            int jj = 1 + ty + k * 8, ii = 1 + tx;
            float m = xs[jj - 1][ii - 1];
            m = fmaxf(m, xs[jj - 1][ii    ]);
            m = fmaxf(m, xs[jj - 1][ii + 1]);
            m = fmaxf(m, xs[jj    ][ii - 1]);
            m = fmaxf(m, xs[jj    ][ii    ]);
            m = fmaxf(m, xs[jj    ][ii + 1]);
            m = fmaxf(m, xs[jj + 1][ii - 1]);
            m = fmaxf(m, xs[jj + 1][ii    ]);
            m = fmaxf(m, xs[jj + 1][ii + 1]);
            M[k]  = m;
            xx[k] = xs[jj][ii];
            pre[k] = __fsub_rn(m, xx[k]) > 0.05f;
        }
        int anyPre = __syncthreads_or((pre[0] || pre[1]) ? 1 : 0);

        float gd[2];
        bool  pos[2] = {false, false};
        int   any = 0;
        if (anyPre) {
            // ==== exact pos test (loads good; coalesced) ====
            #pragma unroll
            for (int k = 0; k < 2; k++) {
                int jj = 1 + ty + k * 8, ii = 1 + tx;
                int r = r0 + jj - 1, c = c0 + ii - 1;
                gd[k] = good[r * WW + c];
                pos[k] = pre[k] &&
                         (__fsub_rn(__fmul_rn(M[k], gd[k]), xx[k]) > 0.05f);
                unsigned rowmask = __ballot_sync(0xffffffffu, pos[k]);
                if (tx == 0) s_rowpos[ty + k * 8] = rowmask;
            }
            any = __syncthreads_or((pos[0] || pos[1]) ? 1 : 0);
        }

        if (!any) {
            // no update possible -> refresh out buffer only if stale
            if (selfchg) {
                #pragma unroll
                for (int k = 0; k < 2; k++) {
                    int jj = 1 + ty + k * 8, ii = 1 + tx;
                    int r = r0 + jj - 1, c = c0 + ii - 1;
                    xout[r * WW + c] = xx[k];
                }
            }
            if (tid == 0 && ((posw >> bx) & 1ull))
                atomicAnd(&g_posmask[by], ~(1ull << bx));
            continue;
        }

        // ==== fill noised tile, cipher gated on pos-mask dilated 1 px ====
        #pragma unroll
        for (int k = 0; k < 3; k++) {
            int s = tid + k * 256;
            bool sv = s < NSLOT;
            int ss = sv ? s : 0;
            int j = ss / SW, ii = ss % SW;
            float x = sv ? xs[j][ii] : 0.0f;
            unsigned rm = 0;
            #pragma unroll
            for (int dr = 0; dr < 3; dr++) {
                int cr = j - 2 + dr;
                if (cr >= 0 && cr < TH) rm |= s_rowpos[cr];
            }
            ull rm2 = ((ull)rm) << 2;
            bool needc = (((rm2 >> ii) & 7ull) != 0ull) && (x > 0.0f);
            float y1 = 0.0f;
            if (__ballot_sync(0xffffffffu, needc)) {
                int r = r0 - 1 + j, c = c0 - 1 + ii;
                uint32_t p = (uint32_t)(min(max(r, 0), HH - 1) * WW +
                                        min(max(c, 0), WW - 1));
                float u = bits_to_uniform(pbits(k1a, k1b, p));
                float f = __fadd_rn(0.9999f, __fmul_rn(1e-4f, u));
                y1 = __fmul_rn(x, f);
            }
            if (sv) ys[j][ii] = y1;
        }
        __syncthreads();

        // ==== maxpool + coin (cipher gated on pos) + write ====
        int fl = 0;
        #pragma unroll
        for (int k = 0; k < 2; k++) {
            int jj = 1 + ty + k * 8, ii = 1 + tx;
            float m = ys[jj - 1][ii - 1];
            m = fmaxf(m, ys[jj - 1][ii    ]);
            m = fmaxf(m, ys[jj - 1][ii + 1]);
            m = fmaxf(m, ys[jj    ][ii - 1]);
            m = fmaxf(m, ys[jj    ][ii    ]);
            m = fmaxf(m, ys[jj    ][ii + 1]);
            m = fmaxf(m, ys[jj + 1][ii - 1]);
            m = fmaxf(m, ys[jj + 1][ii    ]);
            m = fmaxf(m, ys[jj + 1][ii + 1]);

            int jrow = ty + k * 8;               // 0..15 within tile
            int r = r0 + jrow, c = c0 + tx;
            uint32_t p = (uint32_t)(r * WW + c);
            float y4 = 0.0f;
            if (__ballot_sync(0xffffffffu, pos[k])) {
                uint32_t bits = pbits(k2a, k2b, p);
                bool coin = ((bits >> 9) > 0x400000u);   // u > 0.5 strictly
                if (coin && m > 0.0f) y4 = __fmul_rn(m, gd[k]);
            }
            float d  = __fsub_rn(y4, xx[k]);
            float y5 = (d > 0.05f) ? y4 : 0.0f;
            float out = fmaxf(y5, xx[k]);
            xout[p] = out;
            if (out != xx[k]) {
                fl |= 1;
                if (jrow == 0)      fl |= 2;     // top row
                if (jrow == TH - 1) fl |= 4;     // bottom row
                if (tx == 0)        fl |= 8;     // left col
                if (tx == TW - 1)   fl |= 16;    // right col
            }
        }
        if (fl) atomicOr(&s_flags, fl);
        __syncthreads();
        if (tid == 0) {
            ull bit = 1ull << bx;
            int f = s_flags;
            if (f & 1)  atomicOr(&g_ch[cur][0][by], bit);
            if (f & 2)  atomicOr(&g_ch[cur][1][by], bit);
            if (f & 4)  atomicOr(&g_ch[cur][2][by], bit);
            if (f & 8)  atomicOr(&g_ch[cur][3][by], bit);
            if (f & 16) atomicOr(&g_ch[cur][4][by], bit);
            if (!((posw >> bx) & 1ull)) atomicOr(&g_posmask[by], bit);
        }
    }
}

// ---------------------------------------------------------------------------
// Host: per-iteration key schedule (fold_in + partitionable split), ping-pong
// data buffers, 3-parity edge-resolved changed masks. 101 launches total.
// ---------------------------------------------------------------------------
extern "C" void kernel_launch(void* const* d_in, const int* in_sizes, int n_in,
                              void* d_out, int out_size) {
    const float* seed = (const float*)d_in[0];
    const float* hab  = (const float*)d_in[1];
    const float* good = (const float*)d_in[2];
    float* xout = (float*)d_out;

    float* scratch = nullptr;
    cudaGetSymbolAddress((void**)&scratch, g_scratch);

    init_kernel<<<(NPIX / 4 + 255) / 256, 256>>>(seed, hab, good, xout);

    for (int i = 0; i < 100; i++) {
        // fold_in(key(42)=(0,42), i) = cipher((0,42), (0,i))
        uint32_t f0, f1;
        tf2x32(0u, 42u, 0u, (uint32_t)i, f0, f1);
        // partitionable split: k1 = cipher(f,(0,0)), k2 = cipher(f,(0,1))
        uint32_t k1a, k1b, k2a, k2b;
        tf2x32(f0, f1, 0u, 0u, k1a, k1b);
        tf2x32(f0, f1, 0u, 1u, k2a, k2b);

        const int cur = i % 3, prev = (i + 2) % 3, nxt = (i + 1) % 3;
        const float* xin = (i & 1) ? scratch : xout;
        float*       xo  = (i & 1) ? xout    : scratch;

        step_kernel<<<STEP_GRID, 256>>>(xin, xo, good, k1a, k1b, k2a, k2b,
                                        prev, cur, nxt);
    }
    // i = 99 (odd) wrote into xout -> final state lands in d_out
}